// round 5
// baseline (speedup 1.0000x reference)
#include <cuda_runtime.h>
#include <cuda_bf16.h>
#include <cstdint>

#define N_NODES 20000
#define N_EDGES 200000
#define FEAT    128
#define NB      8
#define SI      16
#define SO      16
#define NREL    230
#define WROW    (NB*SI*SO)       // 2048 floats per relation
#define NSUB    32               // sub-counters per relation
#define NCNT    (NREL*NSUB)      // 7360
#define EPG     64               // edges per group (two warps per group)
#define NGROUPS (N_EDGES/EPG)    // 3125

// ---------------- packed f32x2 helpers (Blackwell sm_103a) --------------------
#define PACK_F32X2(out, lo, hi) \
    asm("mov.b64 %0, {%1, %2};" : "=l"(out) : "f"(lo), "f"(hi))
#define UNPACK_F32X2(lo, hi, in) \
    asm("mov.b64 {%0, %1}, %2;" : "=f"(lo), "=f"(hi) : "l"(in))
#define FMA_F32X2(d, a, b, c) \
    asm("fma.rn.f32x2 %0, %1, %2, %3;" : "=l"(d) : "l"(a), "l"(b), "l"(c))

// ---------------- scratch (device globals) -------------------------------------
__device__ float g_agg[(size_t)N_NODES * FEAT];      // 10.24 MB
__device__ int   g_counts[NCNT];                     // zero at load; re-zeroed by scan
__device__ int   g_cursor[NCNT];
__device__ int   g_rank[N_EDGES];                    // intra-bucket rank per edge
__device__ int4  g_edge[N_EDGES];                    // sorted {src,dst,type,norm}

// ---------------- K0: zero agg + histogram-with-rank ---------------------------
__global__ void zero_hist_kernel(const int* __restrict__ etype) {
    int i = blockIdx.x * blockDim.x + threadIdx.x;
    const int n4 = N_NODES * FEAT / 4;   // 640000
    if (i < n4) reinterpret_cast<float4*>(g_agg)[i] =
        make_float4(0.f, 0.f, 0.f, 0.f);
    if (i < N_EDGES) {
        int t = etype[i];
        int r = atomicAdd(&g_counts[t * NSUB + (i & (NSUB - 1))], 1);
        g_rank[i] = r;
    }
}

// ---------------- K1: exclusive scan over 7360 counters + reset ----------------
__global__ void __launch_bounds__(1024) scan_kernel() {
    __shared__ int sp[1024];
    int t = threadIdx.x;
    int base = t * 8;
    int v[8];
    int sum = 0;
    #pragma unroll
    for (int i = 0; i < 8; ++i) {
        if (base + i < NCNT) {
            v[i] = g_counts[base + i];
            g_counts[base + i] = 0;          // reset for next graph replay
        } else v[i] = 0;
        sum += v[i];
    }
    sp[t] = sum;
    __syncthreads();
    #pragma unroll
    for (int off = 1; off < 1024; off <<= 1) {
        int x = (t >= off) ? sp[t - off] : 0;
        __syncthreads();
        sp[t] += x;
        __syncthreads();
    }
    int run = sp[t] - sum;
    #pragma unroll
    for (int i = 0; i < 8; ++i) {
        if (base + i < NCNT) g_cursor[base + i] = run;
        run += v[i];
    }
}

// ---------------- K2: atomic-free scatter ----------------------------------------
__global__ void scatter_kernel(const int* __restrict__ etype,
                               const int* __restrict__ esrc,
                               const int* __restrict__ edst,
                               const float* __restrict__ enorm) {
    int e = blockIdx.x * blockDim.x + threadIdx.x;
    if (e < N_EDGES) {
        int t = etype[e];
        int c = t * NSUB + (e & (NSUB - 1));
        int pos = __ldg(&g_cursor[c]) + g_rank[e];
        g_edge[pos] = make_int4(esrc[e], edst[e], t, __float_as_int(enorm[e]));
    }
}

// ---------------- K3: edge message + vector scatter-add --------------------------
// Two warps per 64-edge group: warp parity p covers channels [64p, 64p+64).
// Lane owns 2 channels c0 = 64p + lane*2, c1 = c0+1 (block b = c0>>4).
// Weights cached as k-pair f32x2 (W[2j][c], W[2j+1][c]); h float4 register pairs
// are directly valid f32x2 operands -> zero packing in the hot loop.
__global__ void __launch_bounds__(128, 7) edge_kernel(
    const float* __restrict__ h,
    const float* __restrict__ weight)
{
    const int gw = blockIdx.x * 4 + (threadIdx.x >> 5);
    const int g  = gw >> 1;
    if (g >= NGROUPS) return;
    const int p    = gw & 1;
    const int lane = threadIdx.x & 31;
    const int e0   = g * EPG;

    const int c0 = p * 64 + lane * 2;
    const int b  = c0 >> 4;
    const int oo = c0 & 15;          // even

    unsigned long long w0[8], w1[8];
    int cur = -1;

    #pragma unroll 1
    for (int i = 0; i < EPG; ++i) {
        int4 rec = __ldg(&g_edge[e0 + i]);     // broadcast across warp
        if (rec.z != cur) {
            cur = rec.z;
            const float* wp = weight + (size_t)cur * WROW + b * (SI * SO) + oo;
            #pragma unroll
            for (int j = 0; j < 8; ++j) {
                float2 ka = __ldg(reinterpret_cast<const float2*>(wp + (2*j)   * SO));
                float2 kb = __ldg(reinterpret_cast<const float2*>(wp + (2*j+1) * SO));
                PACK_F32X2(w0[j], ka.x, kb.x);   // channel c0: (W[2j], W[2j+1])
                PACK_F32X2(w1[j], ka.y, kb.y);   // channel c1
            }
        }

        const ulonglong2* hp = reinterpret_cast<const ulonglong2*>(
            h + (size_t)rec.x * FEAT + b * SI);
        ulonglong2 q0 = __ldg(hp + 0);   // (x0,x1),(x2,x3) as f32x2 pairs
        ulonglong2 q1 = __ldg(hp + 1);
        ulonglong2 q2 = __ldg(hp + 2);
        ulonglong2 q3 = __ldg(hp + 3);

        unsigned long long a0 = 0ULL, a1 = 0ULL;
        FMA_F32X2(a0, q0.x, w0[0], a0);  FMA_F32X2(a1, q0.x, w1[0], a1);
        FMA_F32X2(a0, q0.y, w0[1], a0);  FMA_F32X2(a1, q0.y, w1[1], a1);
        FMA_F32X2(a0, q1.x, w0[2], a0);  FMA_F32X2(a1, q1.x, w1[2], a1);
        FMA_F32X2(a0, q1.y, w0[3], a0);  FMA_F32X2(a1, q1.y, w1[3], a1);
        FMA_F32X2(a0, q2.x, w0[4], a0);  FMA_F32X2(a1, q2.x, w1[4], a1);
        FMA_F32X2(a0, q2.y, w0[5], a0);  FMA_F32X2(a1, q2.y, w1[5], a1);
        FMA_F32X2(a0, q3.x, w0[6], a0);  FMA_F32X2(a1, q3.x, w1[6], a1);
        FMA_F32X2(a0, q3.y, w0[7], a0);  FMA_F32X2(a1, q3.y, w1[7], a1);

        float s0l, s0h, s1l, s1h;
        UNPACK_F32X2(s0l, s0h, a0);
        UNPACK_F32X2(s1l, s1h, a1);
        float en = __int_as_float(rec.w);
        float r0 = (s0l + s0h) * en;
        float r1 = (s1l + s1h) * en;

        float* dst = g_agg + (size_t)rec.y * FEAT + c0;
        asm volatile("red.global.add.v2.f32 [%0], {%1, %2};"
                     :: "l"(dst), "f"(r0), "f"(r1) : "memory");
    }
}

// ---------------- K4: self-loop GEMM + epilogue + time-embedding ---------------
#define MT 64
#define KT 32
__global__ void __launch_bounds__(256) final_kernel(
    const float* __restrict__ h,
    const float* __restrict__ node_norm,
    const float* __restrict__ h_bias,
    const float* __restrict__ loop_weight,
    const float* __restrict__ time_embed,
    const int*   __restrict__ time_idx,
    float*       __restrict__ out)
{
    __shared__ float sW[KT][FEAT];           // 16 KB
    __shared__ float sH[MT][KT + 4];         // 16B-aligned row stride

    const int tid = threadIdx.x;
    const int tm  = tid >> 5;
    const int to  = tid & 31;
    const int n0  = blockIdx.x * MT;

    unsigned long long acc01[8], acc23[8];
    #pragma unroll
    for (int r = 0; r < 8; ++r) { acc01[r] = 0ULL; acc23[r] = 0ULL; }

    for (int kt = 0; kt < FEAT / KT; ++kt) {
        #pragma unroll
        for (int j = 0; j < 4; ++j) {
            int idx = tid + j * 256;
            int r   = idx >> 5;
            int c4  = idx & 31;
            float4 v = __ldg(reinterpret_cast<const float4*>(
                loop_weight + (size_t)(kt * KT + r) * FEAT + c4 * 4));
            *reinterpret_cast<float4*>(&sW[r][c4 * 4]) = v;
        }
        #pragma unroll
        for (int j = 0; j < 2; ++j) {
            int idx = tid + j * 256;
            int r   = idx >> 3;
            int c4  = idx & 7;
            int n   = n0 + r;
            float4 v = make_float4(0.f, 0.f, 0.f, 0.f);
            if (n < N_NODES)
                v = __ldg(reinterpret_cast<const float4*>(
                        h + (size_t)n * FEAT + kt * KT + c4 * 4));
            *reinterpret_cast<float4*>(&sH[r][c4 * 4]) = v;
        }
        __syncthreads();

        #pragma unroll
        for (int k = 0; k < KT; k += 4) {
            ulonglong2 wv0 = *reinterpret_cast<const ulonglong2*>(&sW[k + 0][to * 4]);
            ulonglong2 wv1 = *reinterpret_cast<const ulonglong2*>(&sW[k + 1][to * 4]);
            ulonglong2 wv2 = *reinterpret_cast<const ulonglong2*>(&sW[k + 2][to * 4]);
            ulonglong2 wv3 = *reinterpret_cast<const ulonglong2*>(&sW[k + 3][to * 4]);
            #pragma unroll
            for (int r = 0; r < 8; ++r) {
                float4 hv = *reinterpret_cast<const float4*>(&sH[tm * 8 + r][k]);
                unsigned long long h2;
                PACK_F32X2(h2, hv.x, hv.x);
                FMA_F32X2(acc01[r], h2, wv0.x, acc01[r]);
                FMA_F32X2(acc23[r], h2, wv0.y, acc23[r]);
                PACK_F32X2(h2, hv.y, hv.y);
                FMA_F32X2(acc01[r], h2, wv1.x, acc01[r]);
                FMA_F32X2(acc23[r], h2, wv1.y, acc23[r]);
                PACK_F32X2(h2, hv.z, hv.z);
                FMA_F32X2(acc01[r], h2, wv2.x, acc01[r]);
                FMA_F32X2(acc23[r], h2, wv2.y, acc23[r]);
                PACK_F32X2(h2, hv.w, hv.w);
                FMA_F32X2(acc01[r], h2, wv3.x, acc01[r]);
                FMA_F32X2(acc23[r], h2, wv3.y, acc23[r]);
            }
        }
        __syncthreads();
    }

    const int o0 = to * 4;
    float4 hb = __ldg(reinterpret_cast<const float4*>(h_bias + o0));
    #pragma unroll
    for (int r = 0; r < 8; ++r) {
        int n = n0 + tm * 8 + r;
        if (n < N_NODES) {
            float nn = __ldg(&node_norm[n]);
            float4 ag = *reinterpret_cast<const float4*>(&g_agg[(size_t)n * FEAT + o0]);
            float a0, a1, a2, a3;
            UNPACK_F32X2(a0, a1, acc01[r]);
            UNPACK_F32X2(a2, a3, acc23[r]);
            float4 res;
            res.x = fmaxf(a0 + ag.x * nn + hb.x, 0.f);
            res.y = fmaxf(a1 + ag.y * nn + hb.y, 0.f);
            res.z = fmaxf(a2 + ag.z * nn + hb.z, 0.f);
            res.w = fmaxf(a3 + ag.w * nn + hb.w, 0.f);
            *reinterpret_cast<float4*>(out + (size_t)n * FEAT + o0) = res;
        }
    }

    float* out2 = out + (size_t)N_NODES * FEAT;
    #pragma unroll
    for (int j = 0; j < 8; ++j) {
        int idx = tid + j * 256;
        int r   = idx >> 5;
        int c4  = idx & 31;
        int n   = n0 + r;
        if (n < N_NODES) {
            int ti = __ldg(&time_idx[n]);
            float4 v = __ldg(reinterpret_cast<const float4*>(
                time_embed + (size_t)ti * FEAT + c4 * 4));
            *reinterpret_cast<float4*>(out2 + (size_t)n * FEAT + c4 * 4) = v;
        }
    }
}

// ---------------- launch ---------------------------------------------------------
extern "C" void kernel_launch(void* const* d_in, const int* in_sizes, int n_in,
                              void* d_out, int out_size) {
    const float* h           = (const float*)d_in[0];
    const float* edge_norm   = (const float*)d_in[1];
    const float* node_norm   = (const float*)d_in[2];
    const float* weight      = (const float*)d_in[3];
    const float* h_bias      = (const float*)d_in[4];
    const float* loop_weight = (const float*)d_in[5];
    const float* time_embed  = (const float*)d_in[6];
    const int*   edge_src    = (const int*)d_in[7];
    const int*   edge_dst    = (const int*)d_in[8];
    const int*   edge_type   = (const int*)d_in[9];
    const int*   time_idx    = (const int*)d_in[10];
    float* out = (float*)d_out;

    {
        int n4 = N_NODES * FEAT / 4;     // 640000 threads covers both tasks
        zero_hist_kernel<<<(n4 + 255) / 256, 256>>>(edge_type);
    }
    scan_kernel<<<1, 1024>>>();
    scatter_kernel<<<(N_EDGES + 255) / 256, 256>>>(edge_type, edge_src,
                                                   edge_dst, edge_norm);
    {
        int warps = NGROUPS * 2;                 // 6250
        int ctas  = (warps + 3) / 4;             // 1563
        edge_kernel<<<ctas, 128>>>(h, weight);
    }
    final_kernel<<<(N_NODES + MT - 1) / MT, 256>>>(
        h, node_norm, h_bias, loop_weight, time_embed, time_idx, out);
}